// round 4
// baseline (speedup 1.0000x reference)
#include <cuda_runtime.h>
#include <cuda_bf16.h>
#include <math.h>

#define NN 50000
#define EE 500000
#define IN_DIM 256
#define SLOPE 0.2f
#define NT 8
#define ED 32

// ---------------- scratch (device globals; no allocs allowed) ----------------
__device__ __align__(16) float d_emb1[NN * 256];       // layer1 emb [N,H,D] flat h*64+d
__device__ __align__(16) float d_att1[EE * 4];         // edge weights w = exp(att)
__device__ __align__(16) float d_hl1[NN * 4];
__device__ __align__(16) float d_hr1[NN * 4];

__device__ __align__(16) float d_emb2[NN * 64];
__device__ __align__(16) float d_res2[NN * 64];
__device__ float d_att2[EE];
__device__ float d_hl2[NN];
__device__ float d_hr2[NN];

__device__ __align__(16) float d_he1[NT * 4];
__device__ float d_he2[NT];
__device__ __align__(16) float d_av1[IN_DIM * 4];
__device__ __align__(16) float d_ar1[IN_DIM * 4];

// CSR by destination
__device__ int d_deg[NN];
__device__ int d_ptr[NN + 1];
__device__ int d_cur[NN];
__device__ __align__(8) int2 d_se[EE];                 // (src, edge_id) sorted by dst

// split-bf16 operands
__device__ __align__(16) __nv_bfloat16 d_h_hi[NN * 256];
__device__ __align__(16) __nv_bfloat16 d_h_lo[NN * 256];
__device__ __align__(16) __nv_bfloat16 d_h1_hi[NN * 256];   // layer1 out, H-major
__device__ __align__(16) __nv_bfloat16 d_h1_lo[NN * 256];
__device__ __align__(16) __nv_bfloat16 d_w1t_hi[256 * 256]; // [n][k]
__device__ __align__(16) __nv_bfloat16 d_w1t_lo[256 * 256];
__device__ __align__(16) __nv_bfloat16 d_w2t_hi[128 * 256]; // [n][k], k permuted to H-major
__device__ __align__(16) __nv_bfloat16 d_w2t_lo[128 * 256];

// ---------------- helpers ----------------
__device__ __forceinline__ float lrelu(float x) { return x >= 0.f ? x : SLOPE * x; }

__device__ __forceinline__ unsigned sptr(const void* p) {
    return (unsigned)__cvta_generic_to_shared(p);
}
__device__ __forceinline__ void ldmx4(unsigned* r, unsigned addr) {
    asm volatile("ldmatrix.sync.aligned.m8n8.x4.shared.b16 {%0,%1,%2,%3}, [%4];"
                 : "=r"(r[0]), "=r"(r[1]), "=r"(r[2]), "=r"(r[3]) : "r"(addr));
}
__device__ __forceinline__ void mma_bf16(float* c, const unsigned* a, const unsigned* b) {
    asm volatile("mma.sync.aligned.m16n8k16.row.col.f32.bf16.bf16.f32 "
                 "{%0,%1,%2,%3},{%4,%5,%6,%7},{%8,%9},{%0,%1,%2,%3};"
                 : "+f"(c[0]), "+f"(c[1]), "+f"(c[2]), "+f"(c[3])
                 : "r"(a[0]), "r"(a[1]), "r"(a[2]), "r"(a[3]),
                   "r"(b[0]), "r"(b[1]));
}

// ---------------- init: zero degree counters only ----------------
__global__ void init_kernel() {
    int i = blockIdx.x * blockDim.x + threadIdx.x;
    if (i < NN) d_deg[i] = 0;
}

// ---------------- CSR build ----------------
__global__ void hist_kernel(const int* __restrict__ col) {
    int e = blockIdx.x * blockDim.x + threadIdx.x;
    if (e < EE) atomicAdd(&d_deg[col[e]], 1);
}

__global__ void scan_kernel() {
    __shared__ int sh[1024];
    const int PER = 49;
    int t = threadIdx.x;
    int base = t * PER;
    int local = 0;
    for (int i = 0; i < PER; i++) {
        int n = base + i;
        if (n < NN) local += d_deg[n];
    }
    sh[t] = local;
    __syncthreads();
    for (int off = 1; off < 1024; off <<= 1) {
        int v = (t >= off) ? sh[t - off] : 0;
        __syncthreads();
        sh[t] += v;
        __syncthreads();
    }
    int run = (t > 0) ? sh[t - 1] : 0;
    for (int i = 0; i < PER; i++) {
        int n = base + i;
        if (n < NN) {
            d_ptr[n] = run;
            d_cur[n] = run;
            run += d_deg[n];
        }
    }
    if (t == 0) d_ptr[NN] = EE;
}

__global__ void scatter_kernel(const int* __restrict__ row, const int* __restrict__ col) {
    int e = blockIdx.x * blockDim.x + threadIdx.x;
    if (e >= EE) return;
    int c = col[e];
    int pos = atomicAdd(&d_cur[c], 1);
    d_se[pos] = make_int2(row[e], e);
}

// ---------------- tiny precompute: h_e per etype, attention fold vectors ----------------
__global__ void prep_small(const float* __restrict__ edge_emb1,
                           const float* __restrict__ Wr1,
                           const float* __restrict__ a_e1,
                           const float* __restrict__ edge_emb2,
                           const float* __restrict__ Wr2,
                           const float* __restrict__ a_e2,
                           const float* __restrict__ W1,
                           const float* __restrict__ a_l1,
                           const float* __restrict__ a_r1)
{
    int tid = threadIdx.x;
    {
        int k = tid >> 2, hh = tid & 3;
        float sl = 0.f, sr = 0.f;
        for (int d = 0; d < 64; d++) {
            float w = W1[k * 256 + hh * 64 + d];
            sl += w * a_l1[hh * 64 + d];
            sr += w * a_r1[hh * 64 + d];
        }
        d_av1[tid] = sl;
        d_ar1[tid] = sr;
    }
    if (tid < NT * 4) {
        int t = tid >> 2, h = tid & 3;
        float s = 0.f;
        for (int ed = 0; ed < ED; ed++) {
            float ee = 0.f;
            for (int e = 0; e < ED; e++)
                ee += edge_emb1[t * ED + e] * Wr1[(t * ED + e) * 128 + h * ED + ed];
            s += ee * a_e1[h * ED + ed];
        }
        d_he1[t * 4 + h] = s;
    } else if (tid < NT * 4 + NT) {
        int t = tid - NT * 4;
        float s = 0.f;
        for (int ed = 0; ed < ED; ed++) {
            float ee = 0.f;
            for (int e = 0; e < ED; e++)
                ee += edge_emb2[t * ED + e] * Wr2[(t * ED + e) * ED + ed];
            s += ee * a_e2[ed];
        }
        d_he2[t] = s;
    }
}

// ---------------- weight transpose + hi/lo split; W2 rows permuted to H-major k ----------------
__global__ void prep_w(const float* __restrict__ W1,
                       const float* __restrict__ W2,
                       const float* __restrict__ res_W2)
{
    int idx = blockIdx.x * blockDim.x + threadIdx.x;
    if (idx < 256 * 256) {
        int n = idx >> 8, k = idx & 255;
        float v = W1[k * 256 + n];
        __nv_bfloat16 hi = __float2bfloat16(v);
        __nv_bfloat16 lo = __float2bfloat16(v - __bfloat162float(hi));
        d_w1t_hi[n * 256 + k] = hi;
        d_w1t_lo[n * 256 + k] = lo;
    }
    if (idx < 128 * 256) {
        int n = idx >> 8, k = idx & 255;          // k is H-major (h*64+d)
        int kd = (k & 63) * 4 + (k >> 6);          // D-major row of original W2
        float v = (n < 64) ? W2[kd * 64 + n] : res_W2[kd * 64 + (n - 64)];
        __nv_bfloat16 hi = __float2bfloat16(v);
        __nv_bfloat16 lo = __float2bfloat16(v - __bfloat162float(hi));
        d_w2t_hi[n * 256 + k] = hi;
        d_w2t_lo[n * 256 + k] = lo;
    }
}

// ---------------- split h into hi/lo bf16 ----------------
__global__ void prep_h(const float* __restrict__ h) {
    int idx = blockIdx.x * blockDim.x + threadIdx.x;   // one float4 each
    if (idx >= NN * 64) return;
    float4 v = *reinterpret_cast<const float4*>(&h[(size_t)idx * 4]);
    __nv_bfloat16 hi[4], lo[4];
    float* vp = &v.x;
#pragma unroll
    for (int j = 0; j < 4; j++) {
        hi[j] = __float2bfloat16(vp[j]);
        lo[j] = __float2bfloat16(vp[j] - __bfloat162float(hi[j]));
    }
    *reinterpret_cast<uint2*>(&d_h_hi[(size_t)idx * 4]) = *reinterpret_cast<uint2*>(hi);
    *reinterpret_cast<uint2*>(&d_h_lo[(size_t)idx * 4]) = *reinterpret_cast<uint2*>(lo);
}

// ---------------- tensor-core GEMM, split-bf16 A and B (3 MMAs) ----------------
// MODE 0: C0 ld=256 (layer1). MODE 1: cols [0,64)->C0, [64,128)->C1, ld=64.
template<int MODE>
__global__ void __launch_bounds__(256) mma_gemm(const __nv_bfloat16* __restrict__ Ahi,
                                                const __nv_bfloat16* __restrict__ Alo,
                                                const __nv_bfloat16* __restrict__ Bhi,
                                                const __nv_bfloat16* __restrict__ Blo,
                                                float* __restrict__ C0,
                                                float* __restrict__ C1,
                                                int M)
{
    __shared__ __nv_bfloat16 As[2][128][40];
    __shared__ __nv_bfloat16 Bs[2][128][40];

    const int tid = threadIdx.x;
    const int lane = tid & 31;
    const int warp = tid >> 5;
    const int wm = warp & 1;
    const int wn = warp >> 1;
    const int rowBase = blockIdx.y * 128;
    const int colBase = blockIdx.x * 128;

    float acc[4][4][4];
#pragma unroll
    for (int i = 0; i < 4; i++)
#pragma unroll
        for (int j = 0; j < 4; j++)
#pragma unroll
            for (int q = 0; q < 4; q++) acc[i][j][q] = 0.f;

    const int grp = lane >> 3;
    const int arow = (lane & 7) + ((grp & 1) << 3);
    const int acol = (grp >> 1) << 3;
    const int brow = (lane & 7) + ((grp >> 1) << 3);
    const int bcol = (grp & 1) << 3;

    for (int k0 = 0; k0 < 256; k0 += 32) {
        // A tiles: 128 rows x 32 k bf16, 2 splits; 16B per thread x2 per split
#pragma unroll
        for (int it = 0; it < 2; it++) {
            int lin = tid + it * 256;
            int r = lin >> 2;
            int c = (lin & 3) * 8;
            uint4 zh = make_uint4(0, 0, 0, 0), zl = make_uint4(0, 0, 0, 0);
            if (rowBase + r < M) {
                size_t off = (size_t)(rowBase + r) * 256 + k0 + c;
                zh = *reinterpret_cast<const uint4*>(&Ahi[off]);
                zl = *reinterpret_cast<const uint4*>(&Alo[off]);
            }
            *reinterpret_cast<uint4*>(&As[0][r][c]) = zh;
            *reinterpret_cast<uint4*>(&As[1][r][c]) = zl;
        }
        // B tiles
#pragma unroll
        for (int it = 0; it < 2; it++) {
            int lin = tid + it * 256;
            int r = lin >> 2;
            int c = (lin & 3) * 8;
            size_t off = (size_t)(colBase + r) * 256 + k0 + c;
            *reinterpret_cast<uint4*>(&Bs[0][r][c]) = *reinterpret_cast<const uint4*>(&Bhi[off]);
            *reinterpret_cast<uint4*>(&Bs[1][r][c]) = *reinterpret_cast<const uint4*>(&Blo[off]);
        }
        __syncthreads();

#pragma unroll
        for (int ks = 0; ks < 2; ks++) {
            unsigned afr[4][2][4];
            unsigned bfr[4][2][2];
#pragma unroll
            for (int mt = 0; mt < 4; mt++)
#pragma unroll
                for (int s = 0; s < 2; s++)
                    ldmx4(afr[mt][s], sptr(&As[s][wm * 64 + mt * 16 + arow][ks * 16 + acol]));
#pragma unroll
            for (int np = 0; np < 2; np++)
#pragma unroll
                for (int s = 0; s < 2; s++) {
                    unsigned r4[4];
                    ldmx4(r4, sptr(&Bs[s][wn * 32 + np * 16 + brow][ks * 16 + bcol]));
                    bfr[np * 2 + 0][s][0] = r4[0]; bfr[np * 2 + 0][s][1] = r4[1];
                    bfr[np * 2 + 1][s][0] = r4[2]; bfr[np * 2 + 1][s][1] = r4[3];
                }
#pragma unroll
            for (int mt = 0; mt < 4; mt++)
#pragma unroll
                for (int nt = 0; nt < 4; nt++) {
                    mma_bf16(acc[mt][nt], afr[mt][0], bfr[nt][0]);
                    mma_bf16(acc[mt][nt], afr[mt][0], bfr[nt][1]);
                    mma_bf16(acc[mt][nt], afr[mt][1], bfr[nt][0]);
                }
        }
        __syncthreads();
    }

#pragma unroll
    for (int mt = 0; mt < 4; mt++) {
#pragma unroll
        for (int nt = 0; nt < 4; nt++) {
            int cc = colBase + wn * 32 + nt * 8 + (lane & 3) * 2;
#pragma unroll
            for (int hh = 0; hh < 2; hh++) {
                int gm = rowBase + wm * 64 + mt * 16 + (lane >> 2) + hh * 8;
                if (gm >= M) continue;
                float2 v = make_float2(acc[mt][nt][hh * 2], acc[mt][nt][hh * 2 + 1]);
                if (MODE == 0) {
                    *reinterpret_cast<float2*>(&C0[(size_t)gm * 256 + cc]) = v;
                } else {
                    if (cc < 64)
                        *reinterpret_cast<float2*>(&C0[(size_t)gm * 64 + cc]) = v;
                    else
                        *reinterpret_cast<float2*>(&C1[(size_t)gm * 64 + cc - 64]) = v;
                }
            }
        }
    }
}

// ---------------- layer1 node dots, folded: warp per node ----------------
__global__ void __launch_bounds__(256) hlr1_kernel(const float* __restrict__ h)
{
    int gid = blockIdx.x * blockDim.x + threadIdx.x;
    int n = gid >> 5;
    int lane = gid & 31;
    if (n >= NN) return;
    float al[4] = {}, ar[4] = {};
#pragma unroll
    for (int it = 0; it < 8; it++) {
        int k = it * 32 + lane;
        float v = h[(size_t)n * 256 + k];
        float4 a = *reinterpret_cast<const float4*>(&d_av1[k * 4]);
        float4 r = *reinterpret_cast<const float4*>(&d_ar1[k * 4]);
        al[0] += v * a.x; al[1] += v * a.y; al[2] += v * a.z; al[3] += v * a.w;
        ar[0] += v * r.x; ar[1] += v * r.y; ar[2] += v * r.z; ar[3] += v * r.w;
    }
#pragma unroll
    for (int off = 16; off > 0; off >>= 1) {
#pragma unroll
        for (int j = 0; j < 4; j++) {
            al[j] += __shfl_xor_sync(0xffffffffu, al[j], off);
            ar[j] += __shfl_xor_sync(0xffffffffu, ar[j], off);
        }
    }
    if (lane == 0) {
        *reinterpret_cast<float4*>(&d_hl1[n * 4]) = make_float4(al[0], al[1], al[2], al[3]);
        *reinterpret_cast<float4*>(&d_hr1[n * 4]) = make_float4(ar[0], ar[1], ar[2], ar[3]);
    }
}

// ---------------- layer1 attention weights (no atomics) ----------------
__global__ void att1_kernel(const int* __restrict__ row, const int* __restrict__ col,
                            const int* __restrict__ et)
{
    int e = blockIdx.x * blockDim.x + threadIdx.x;
    if (e >= EE) return;
    int r = row[e], c = col[e], t = et[e];
    float4 l = *reinterpret_cast<const float4*>(&d_hl1[r * 4]);
    float4 rr = *reinterpret_cast<const float4*>(&d_hr1[c * 4]);
    float4 he = *reinterpret_cast<const float4*>(&d_he1[t * 4]);
    float w0 = __expf(lrelu(l.x + rr.x + he.x));
    float w1 = __expf(lrelu(l.y + rr.y + he.y));
    float w2 = __expf(lrelu(l.z + rr.z + he.z));
    float w3 = __expf(lrelu(l.w + rr.w + he.w));
    *reinterpret_cast<float4*>(&d_att1[(size_t)e * 4]) = make_float4(w0, w1, w2, w3);
}

// ---------------- layer1 CSR aggregate + normalize + ELU + split-bf16 write ----------------
// Warp per dst node. Lane l owns emb floats [l*8, l*8+8) -> head l>>3.
__global__ void __launch_bounds__(256) agg1fin_kernel()
{
    int gid = blockIdx.x * blockDim.x + threadIdx.x;
    int n = gid >> 5;
    int lane = gid & 31;
    if (n >= NN) return;
    int beg = d_ptr[n], end = d_ptr[n + 1];
    int hsel = lane >> 3;
    float acc[8] = {};
    float wsum = 0.f;

    int2 se_next = (beg < end) ? d_se[beg] : make_int2(0, 0);
    for (int j = beg; j < end; j++) {
        int2 se = se_next;
        if (j + 1 < end) se_next = d_se[j + 1];
        float wc = d_att1[(size_t)se.y * 4 + hsel];
        const float4* p = reinterpret_cast<const float4*>(&d_emb1[(size_t)se.x * 256 + lane * 8]);
        float4 v0 = p[0];
        float4 v1 = p[1];
        wsum += wc;
        acc[0] += v0.x * wc; acc[1] += v0.y * wc; acc[2] += v0.z * wc; acc[3] += v0.w * wc;
        acc[4] += v1.x * wc; acc[5] += v1.y * wc; acc[6] += v1.z * wc; acc[7] += v1.w * wc;
    }
    float inv = (wsum > 0.f) ? 1.f / wsum : 0.f;
    __nv_bfloat16 hi8[8], lo8[8];
#pragma unroll
    for (int i = 0; i < 8; i++) {
        float v = acc[i] * inv;
        v = (v > 0.f) ? v : expm1f(v);     // elu
        hi8[i] = __float2bfloat16(v);
        lo8[i] = __float2bfloat16(v - __bfloat162float(hi8[i]));
    }
    *reinterpret_cast<uint4*>(&d_h1_hi[(size_t)n * 256 + lane * 8]) = *reinterpret_cast<uint4*>(hi8);
    *reinterpret_cast<uint4*>(&d_h1_lo[(size_t)n * 256 + lane * 8]) = *reinterpret_cast<uint4*>(lo8);
}

// ---------------- layer2 node dots: warp per node ----------------
__global__ void nodedot2(const float* __restrict__ a_l, const float* __restrict__ a_r)
{
    int gid = blockIdx.x * blockDim.x + threadIdx.x;
    int n = gid >> 5;
    int lane = gid & 31;
    if (n >= NN) return;
    float2 v = *reinterpret_cast<const float2*>(&d_emb2[(size_t)n * 64 + lane * 2]);
    float2 al = *reinterpret_cast<const float2*>(&a_l[lane * 2]);
    float2 ar = *reinterpret_cast<const float2*>(&a_r[lane * 2]);
    float sl = v.x * al.x + v.y * al.y;
    float sr = v.x * ar.x + v.y * ar.y;
#pragma unroll
    for (int off = 16; off > 0; off >>= 1) {
        sl += __shfl_xor_sync(0xffffffffu, sl, off);
        sr += __shfl_xor_sync(0xffffffffu, sr, off);
    }
    if (lane == 0) { d_hl2[n] = sl; d_hr2[n] = sr; }
}

__global__ void att2_kernel(const int* __restrict__ row, const int* __restrict__ col,
                            const int* __restrict__ et)
{
    int e = blockIdx.x * blockDim.x + threadIdx.x;
    if (e >= EE) return;
    d_att2[e] = __expf(lrelu(d_hl2[row[e]] + d_hr2[col[e]] + d_he2[et[e]]));
}

// ---------------- layer2 CSR aggregate + normalize + residual + bias -> out ----------------
__global__ void __launch_bounds__(256) agg2fin_kernel(const float* __restrict__ res_b2,
                                                      float* __restrict__ out)
{
    int gid = blockIdx.x * blockDim.x + threadIdx.x;
    int n = gid >> 5;
    int lane = gid & 31;
    if (n >= NN) return;
    int beg = d_ptr[n], end = d_ptr[n + 1];
    float ax = 0.f, ay = 0.f, wsum = 0.f;

    int2 se_next = (beg < end) ? d_se[beg] : make_int2(0, 0);
    for (int j = beg; j < end; j++) {
        int2 se = se_next;
        if (j + 1 < end) se_next = d_se[j + 1];
        float w = d_att2[se.y];
        float2 v = *reinterpret_cast<const float2*>(&d_emb2[(size_t)se.x * 64 + lane * 2]);
        wsum += w;
        ax += v.x * w;
        ay += v.y * w;
    }
    float inv = (wsum > 0.f) ? 1.f / wsum : 0.f;
    float2 r = *reinterpret_cast<const float2*>(&d_res2[(size_t)n * 64 + lane * 2]);
    float2 b = *reinterpret_cast<const float2*>(&res_b2[lane * 2]);
    float2 o = make_float2(ax * inv + r.x + b.x, ay * inv + r.y + b.y);
    *reinterpret_cast<float2*>(&out[(size_t)n * 64 + lane * 2]) = o;
}

// ---------------- launch ----------------
extern "C" void kernel_launch(void* const* d_in, const int* in_sizes, int n_in,
                              void* d_out, int out_size)
{
    const float* h         = (const float*)d_in[0];
    const int*   row       = (const int*)d_in[1];
    const int*   col       = (const int*)d_in[2];
    const int*   etype     = (const int*)d_in[3];
    const float* edge_emb1 = (const float*)d_in[4];
    const float* W1        = (const float*)d_in[5];
    const float* Wr1       = (const float*)d_in[6];
    const float* a_l1      = (const float*)d_in[7];
    const float* a_r1      = (const float*)d_in[8];
    const float* a_e1      = (const float*)d_in[9];
    const float* edge_emb2 = (const float*)d_in[10];
    const float* W2        = (const float*)d_in[11];
    const float* Wr2       = (const float*)d_in[12];
    const float* a_l2      = (const float*)d_in[13];
    const float* a_r2      = (const float*)d_in[14];
    const float* a_e2      = (const float*)d_in[15];
    const float* res_W2    = (const float*)d_in[16];
    const float* res_b2    = (const float*)d_in[17];
    float* out = (float*)d_out;

    float *p_emb1, *p_emb2, *p_res2;
    cudaGetSymbolAddress((void**)&p_emb1, d_emb1);
    cudaGetSymbolAddress((void**)&p_emb2, d_emb2);
    cudaGetSymbolAddress((void**)&p_res2, d_res2);
    __nv_bfloat16 *p_w1h, *p_w1l, *p_w2h, *p_w2l, *p_hh, *p_hl, *p_h1h, *p_h1l;
    cudaGetSymbolAddress((void**)&p_w1h, d_w1t_hi);
    cudaGetSymbolAddress((void**)&p_w1l, d_w1t_lo);
    cudaGetSymbolAddress((void**)&p_w2h, d_w2t_hi);
    cudaGetSymbolAddress((void**)&p_w2l, d_w2t_lo);
    cudaGetSymbolAddress((void**)&p_hh, d_h_hi);
    cudaGetSymbolAddress((void**)&p_hl, d_h_lo);
    cudaGetSymbolAddress((void**)&p_h1h, d_h1_hi);
    cudaGetSymbolAddress((void**)&p_h1l, d_h1_lo);

    // ---- prep + CSR build ----
    init_kernel<<<(NN + 255) / 256, 256>>>();
    hist_kernel<<<(EE + 255) / 256, 256>>>(col);
    scan_kernel<<<1, 1024>>>();
    scatter_kernel<<<(EE + 255) / 256, 256>>>(row, col);
    prep_small<<<1, 1024>>>(edge_emb1, Wr1, a_e1, edge_emb2, Wr2, a_e2, W1, a_l1, a_r1);
    prep_w<<<256, 256>>>(W1, W2, res_W2);
    prep_h<<<(NN * 64 + 255) / 256, 256>>>(h);

    // ---- layer 1 ----
    mma_gemm<0><<<dim3(2, 391), 256>>>(p_hh, p_hl, p_w1h, p_w1l, p_emb1, nullptr, NN);
    hlr1_kernel<<<(NN * 32 + 255) / 256, 256>>>(h);
    att1_kernel<<<(EE + 255) / 256, 256>>>(row, col, etype);
    agg1fin_kernel<<<(NN * 32) / 256, 256>>>();

    // ---- layer 2 ----
    mma_gemm<1><<<dim3(1, 391), 256>>>(p_h1h, p_h1l, p_w2h, p_w2l, p_emb2, p_res2, NN);
    nodedot2<<<(NN * 32 + 255) / 256, 256>>>(a_l2, a_r2);
    att2_kernel<<<(EE + 255) / 256, 256>>>(row, col, etype);
    agg2fin_kernel<<<(NN * 32) / 256, 256>>>(res_b2, out);
}

// round 5
// speedup vs baseline: 1.0491x; 1.0491x over previous
#include <cuda_runtime.h>
#include <cuda_bf16.h>
#include <math.h>

#define NN 50000
#define EE 500000
#define IN_DIM 256
#define SLOPE 0.2f
#define NT 8
#define ED 32

// ---------------- scratch (device globals; no allocs allowed) ----------------
__device__ __align__(16) float d_emb1[NN * 256];       // layer1 emb [N,H,D] flat h*64+d
__device__ __align__(16) float d_hl1[NN * 4];
__device__ __align__(16) float d_hr1[NN * 4];

__device__ __align__(16) float d_emb2[NN * 64];
__device__ __align__(16) float d_res2[NN * 64];
__device__ float d_hl2[NN];
__device__ float d_hr2[NN];

__device__ __align__(16) float d_he1[NT * 4];
__device__ float d_he2[NT];
__device__ __align__(16) float d_av1[IN_DIM * 4];
__device__ __align__(16) float d_ar1[IN_DIM * 4];

// CSR by destination; payload = src | (etype << 16)
__device__ int d_deg[NN];
__device__ int d_ptr[NN + 1];
__device__ int d_cur[NN];
__device__ unsigned d_sep[EE];

// split-bf16 operands
__device__ __align__(16) __nv_bfloat16 d_h_hi[NN * 256];
__device__ __align__(16) __nv_bfloat16 d_h_lo[NN * 256];
__device__ __align__(16) __nv_bfloat16 d_h1_hi[NN * 256];   // layer1 out, H-major
__device__ __align__(16) __nv_bfloat16 d_h1_lo[NN * 256];
__device__ __align__(16) __nv_bfloat16 d_w1t_hi[256 * 256]; // [n][k]
__device__ __align__(16) __nv_bfloat16 d_w1t_lo[256 * 256];
__device__ __align__(16) __nv_bfloat16 d_w2t_hi[128 * 256]; // [n][k], k permuted to H-major
__device__ __align__(16) __nv_bfloat16 d_w2t_lo[128 * 256];

// ---------------- helpers ----------------
__device__ __forceinline__ float lrelu(float x) { return x >= 0.f ? x : SLOPE * x; }

__device__ __forceinline__ unsigned sptr(const void* p) {
    return (unsigned)__cvta_generic_to_shared(p);
}
__device__ __forceinline__ void ldmx4(unsigned* r, unsigned addr) {
    asm volatile("ldmatrix.sync.aligned.m8n8.x4.shared.b16 {%0,%1,%2,%3}, [%4];"
                 : "=r"(r[0]), "=r"(r[1]), "=r"(r[2]), "=r"(r[3]) : "r"(addr));
}
__device__ __forceinline__ void mma_bf16(float* c, const unsigned* a, const unsigned* b) {
    asm volatile("mma.sync.aligned.m16n8k16.row.col.f32.bf16.bf16.f32 "
                 "{%0,%1,%2,%3},{%4,%5,%6,%7},{%8,%9},{%0,%1,%2,%3};"
                 : "+f"(c[0]), "+f"(c[1]), "+f"(c[2]), "+f"(c[3])
                 : "r"(a[0]), "r"(a[1]), "r"(a[2]), "r"(a[3]),
                   "r"(b[0]), "r"(b[1]));
}

// ---------------- tiny precompute: h_e per etype, attention fold vectors ----------------
__global__ void prep_small(const float* __restrict__ edge_emb1,
                           const float* __restrict__ Wr1,
                           const float* __restrict__ a_e1,
                           const float* __restrict__ edge_emb2,
                           const float* __restrict__ Wr2,
                           const float* __restrict__ a_e2,
                           const float* __restrict__ W1,
                           const float* __restrict__ a_l1,
                           const float* __restrict__ a_r1)
{
    int tid = threadIdx.x;
    {
        int k = tid >> 2, hh = tid & 3;
        float sl = 0.f, sr = 0.f;
        for (int d = 0; d < 64; d++) {
            float w = W1[k * 256 + hh * 64 + d];
            sl += w * a_l1[hh * 64 + d];
            sr += w * a_r1[hh * 64 + d];
        }
        d_av1[tid] = sl;
        d_ar1[tid] = sr;
    }
    if (tid < NT * 4) {
        int t = tid >> 2, h = tid & 3;
        float s = 0.f;
        for (int ed = 0; ed < ED; ed++) {
            float ee = 0.f;
            for (int e = 0; e < ED; e++)
                ee += edge_emb1[t * ED + e] * Wr1[(t * ED + e) * 128 + h * ED + ed];
            s += ee * a_e1[h * ED + ed];
        }
        d_he1[t * 4 + h] = s;
    } else if (tid < NT * 4 + NT) {
        int t = tid - NT * 4;
        float s = 0.f;
        for (int ed = 0; ed < ED; ed++) {
            float ee = 0.f;
            for (int e = 0; e < ED; e++)
                ee += edge_emb2[t * ED + e] * Wr2[(t * ED + e) * ED + ed];
            s += ee * a_e2[ed];
        }
        d_he2[t] = s;
    }
}

// ---------------- weight transpose + hi/lo split; W2 rows permuted to H-major k ----------------
__global__ void prep_w(const float* __restrict__ W1,
                       const float* __restrict__ W2,
                       const float* __restrict__ res_W2)
{
    int idx = blockIdx.x * blockDim.x + threadIdx.x;
    if (idx < 256 * 256) {
        int n = idx >> 8, k = idx & 255;
        float v = W1[k * 256 + n];
        __nv_bfloat16 hi = __float2bfloat16(v);
        __nv_bfloat16 lo = __float2bfloat16(v - __bfloat162float(hi));
        d_w1t_hi[n * 256 + k] = hi;
        d_w1t_lo[n * 256 + k] = lo;
    }
    if (idx < 128 * 256) {
        int n = idx >> 8, k = idx & 255;           // k is H-major (h*64+d)
        int kd = (k & 63) * 4 + (k >> 6);           // D-major row of original W2
        float v = (n < 64) ? W2[kd * 64 + n] : res_W2[kd * 64 + (n - 64)];
        __nv_bfloat16 hi = __float2bfloat16(v);
        __nv_bfloat16 lo = __float2bfloat16(v - __bfloat162float(hi));
        d_w2t_hi[n * 256 + k] = hi;
        d_w2t_lo[n * 256 + k] = lo;
    }
}

// ---------------- fused: split h into hi/lo bf16 + layer1 node dots ----------------
// Warp per node; lane owns k pair (it*64 + lane*2).
__global__ void __launch_bounds__(256) prep_hlr(const float* __restrict__ h)
{
    int gid = blockIdx.x * blockDim.x + threadIdx.x;
    int n = gid >> 5;
    int lane = gid & 31;
    if (n >= NN) return;
    float al[4] = {}, ar[4] = {};
#pragma unroll
    for (int it = 0; it < 4; it++) {
        int k = it * 64 + lane * 2;
        float2 v = *reinterpret_cast<const float2*>(&h[(size_t)n * 256 + k]);
        float4 a0 = *reinterpret_cast<const float4*>(&d_av1[k * 4]);
        float4 a1 = *reinterpret_cast<const float4*>(&d_av1[k * 4 + 4]);
        float4 r0 = *reinterpret_cast<const float4*>(&d_ar1[k * 4]);
        float4 r1 = *reinterpret_cast<const float4*>(&d_ar1[k * 4 + 4]);
        al[0] += v.x * a0.x + v.y * a1.x; al[1] += v.x * a0.y + v.y * a1.y;
        al[2] += v.x * a0.z + v.y * a1.z; al[3] += v.x * a0.w + v.y * a1.w;
        ar[0] += v.x * r0.x + v.y * r1.x; ar[1] += v.x * r0.y + v.y * r1.y;
        ar[2] += v.x * r0.z + v.y * r1.z; ar[3] += v.x * r0.w + v.y * r1.w;
        __nv_bfloat16 hx = __float2bfloat16(v.x);
        __nv_bfloat16 hy = __float2bfloat16(v.y);
        __nv_bfloat16 lx = __float2bfloat16(v.x - __bfloat162float(hx));
        __nv_bfloat16 ly = __float2bfloat16(v.y - __bfloat162float(hy));
        __nv_bfloat162 hp; hp.x = hx; hp.y = hy;
        __nv_bfloat162 lp; lp.x = lx; lp.y = ly;
        *reinterpret_cast<__nv_bfloat162*>(&d_h_hi[(size_t)n * 256 + k]) = hp;
        *reinterpret_cast<__nv_bfloat162*>(&d_h_lo[(size_t)n * 256 + k]) = lp;
    }
#pragma unroll
    for (int off = 16; off > 0; off >>= 1) {
#pragma unroll
        for (int j = 0; j < 4; j++) {
            al[j] += __shfl_xor_sync(0xffffffffu, al[j], off);
            ar[j] += __shfl_xor_sync(0xffffffffu, ar[j], off);
        }
    }
    if (lane == 0) {
        *reinterpret_cast<float4*>(&d_hl1[n * 4]) = make_float4(al[0], al[1], al[2], al[3]);
        *reinterpret_cast<float4*>(&d_hr1[n * 4]) = make_float4(ar[0], ar[1], ar[2], ar[3]);
    }
}

// ---------------- tensor-core GEMM, split-bf16 A and B (3 MMAs) ----------------
template<int MODE>
__global__ void __launch_bounds__(256) mma_gemm(const __nv_bfloat16* __restrict__ Ahi,
                                                const __nv_bfloat16* __restrict__ Alo,
                                                const __nv_bfloat16* __restrict__ Bhi,
                                                const __nv_bfloat16* __restrict__ Blo,
                                                float* __restrict__ C0,
                                                float* __restrict__ C1,
                                                int M)
{
    __shared__ __nv_bfloat16 As[2][128][40];
    __shared__ __nv_bfloat16 Bs[2][128][40];

    const int tid = threadIdx.x;
    const int lane = tid & 31;
    const int warp = tid >> 5;
    const int wm = warp & 1;
    const int wn = warp >> 1;
    const int rowBase = blockIdx.y * 128;
    const int colBase = blockIdx.x * 128;

    float acc[4][4][4];
#pragma unroll
    for (int i = 0; i < 4; i++)
#pragma unroll
        for (int j = 0; j < 4; j++)
#pragma unroll
            for (int q = 0; q < 4; q++) acc[i][j][q] = 0.f;

    const int grp = lane >> 3;
    const int arow = (lane & 7) + ((grp & 1) << 3);
    const int acol = (grp >> 1) << 3;
    const int brow = (lane & 7) + ((grp >> 1) << 3);
    const int bcol = (grp & 1) << 3;

    for (int k0 = 0; k0 < 256; k0 += 32) {
#pragma unroll
        for (int it = 0; it < 2; it++) {
            int lin = tid + it * 256;
            int r = lin >> 2;
            int c = (lin & 3) * 8;
            uint4 zh = make_uint4(0, 0, 0, 0), zl = make_uint4(0, 0, 0, 0);
            if (rowBase + r < M) {
                size_t off = (size_t)(rowBase + r) * 256 + k0 + c;
                zh = *reinterpret_cast<const uint4*>(&Ahi[off]);
                zl = *reinterpret_cast<const uint4*>(&Alo[off]);
            }
            *reinterpret_cast<uint4*>(&As[0][r][c]) = zh;
            *reinterpret_cast<uint4*>(&As[1][r][c]) = zl;
        }
#pragma unroll
        for (int it = 0; it < 2; it++) {
            int lin = tid + it * 256;
            int r = lin >> 2;
            int c = (lin & 3) * 8;
            size_t off = (size_t)(colBase + r) * 256 + k0 + c;
            *reinterpret_cast<uint4*>(&Bs[0][r][c]) = *reinterpret_cast<const uint4*>(&Bhi[off]);
            *reinterpret_cast<uint4*>(&Bs[1][r][c]) = *reinterpret_cast<const uint4*>(&Blo[off]);
        }
        __syncthreads();

#pragma unroll
        for (int ks = 0; ks < 2; ks++) {
            unsigned afr[4][2][4];
            unsigned bfr[4][2][2];
#pragma unroll
            for (int mt = 0; mt < 4; mt++)
#pragma unroll
                for (int s = 0; s < 2; s++)
                    ldmx4(afr[mt][s], sptr(&As[s][wm * 64 + mt * 16 + arow][ks * 16 + acol]));
#pragma unroll
            for (int np = 0; np < 2; np++)
#pragma unroll
                for (int s = 0; s < 2; s++) {
                    unsigned r4[4];
                    ldmx4(r4, sptr(&Bs[s][wn * 32 + np * 16 + brow][ks * 16 + bcol]));
                    bfr[np * 2 + 0][s][0] = r4[0]; bfr[np * 2 + 0][s][1] = r4[1];
                    bfr[np * 2 + 1][s][0] = r4[2]; bfr[np * 2 + 1][s][1] = r4[3];
                }
#pragma unroll
            for (int mt = 0; mt < 4; mt++)
#pragma unroll
                for (int nt = 0; nt < 4; nt++) {
                    mma_bf16(acc[mt][nt], afr[mt][0], bfr[nt][0]);
                    mma_bf16(acc[mt][nt], afr[mt][0], bfr[nt][1]);
                    mma_bf16(acc[mt][nt], afr[mt][1], bfr[nt][0]);
                }
        }
        __syncthreads();
    }

#pragma unroll
    for (int mt = 0; mt < 4; mt++) {
#pragma unroll
        for (int nt = 0; nt < 4; nt++) {
            int cc = colBase + wn * 32 + nt * 8 + (lane & 3) * 2;
#pragma unroll
            for (int hh = 0; hh < 2; hh++) {
                int gm = rowBase + wm * 64 + mt * 16 + (lane >> 2) + hh * 8;
                if (gm >= M) continue;
                float2 v = make_float2(acc[mt][nt][hh * 2], acc[mt][nt][hh * 2 + 1]);
                if (MODE == 0) {
                    *reinterpret_cast<float2*>(&C0[(size_t)gm * 256 + cc]) = v;
                } else {
                    if (cc < 64)
                        *reinterpret_cast<float2*>(&C0[(size_t)gm * 64 + cc]) = v;
                    else
                        *reinterpret_cast<float2*>(&C1[(size_t)gm * 64 + cc - 64]) = v;
                }
            }
        }
    }
}

// ---------------- CSR build ----------------
__global__ void init_kernel() {
    int i = blockIdx.x * blockDim.x + threadIdx.x;
    if (i < NN) d_deg[i] = 0;
}

__global__ void hist_kernel(const int* __restrict__ col) {
    int e = blockIdx.x * blockDim.x + threadIdx.x;
    if (e < EE) atomicAdd(&d_deg[col[e]], 1);
}

__global__ void scan_kernel() {
    __shared__ int sh[1024];
    const int PER = 49;
    int t = threadIdx.x;
    int base = t * PER;
    int local = 0;
    for (int i = 0; i < PER; i++) {
        int n = base + i;
        if (n < NN) local += d_deg[n];
    }
    sh[t] = local;
    __syncthreads();
    for (int off = 1; off < 1024; off <<= 1) {
        int v = (t >= off) ? sh[t - off] : 0;
        __syncthreads();
        sh[t] += v;
        __syncthreads();
    }
    int run = (t > 0) ? sh[t - 1] : 0;
    for (int i = 0; i < PER; i++) {
        int n = base + i;
        if (n < NN) {
            d_ptr[n] = run;
            d_cur[n] = run;
            run += d_deg[n];
        }
    }
    if (t == 0) d_ptr[NN] = EE;
}

__global__ void scatter_kernel(const int* __restrict__ row, const int* __restrict__ col,
                               const int* __restrict__ et) {
    int e = blockIdx.x * blockDim.x + threadIdx.x;
    if (e >= EE) return;
    int c = col[e];
    int pos = atomicAdd(&d_cur[c], 1);
    d_sep[pos] = (unsigned)row[e] | ((unsigned)et[e] << 16);
}

// ---------------- layer1: fused attention + CSR aggregate + softmax + ELU + split ----------------
// Warp per dst node. Lane l owns emb floats [l*8, l*8+8) -> head l>>3.
__global__ void __launch_bounds__(256) agg1fin_kernel()
{
    int gid = blockIdx.x * blockDim.x + threadIdx.x;
    int n = gid >> 5;
    int lane = gid & 31;
    if (n >= NN) return;
    int beg = d_ptr[n], end = d_ptr[n + 1];
    int hsel = lane >> 3;
    float hr = d_hr1[n * 4 + hsel];
    float acc[8] = {};
    float wsum = 0.f;

    int j = beg;
    for (; j + 1 < end; j += 2) {
        unsigned pa = d_sep[j];
        unsigned pb = d_sep[j + 1];
        int sa = pa & 0xFFFFu, ta = pa >> 16;
        int sb = pb & 0xFFFFu, tb = pb >> 16;
        float wa = __expf(lrelu(d_hl1[sa * 4 + hsel] + hr + d_he1[ta * 4 + hsel]));
        float wb = __expf(lrelu(d_hl1[sb * 4 + hsel] + hr + d_he1[tb * 4 + hsel]));
        const float4* pA = reinterpret_cast<const float4*>(&d_emb1[(size_t)sa * 256 + lane * 8]);
        const float4* pB = reinterpret_cast<const float4*>(&d_emb1[(size_t)sb * 256 + lane * 8]);
        float4 a0 = pA[0], a1 = pA[1];
        float4 b0 = pB[0], b1 = pB[1];
        wsum += wa + wb;
        acc[0] += a0.x * wa + b0.x * wb; acc[1] += a0.y * wa + b0.y * wb;
        acc[2] += a0.z * wa + b0.z * wb; acc[3] += a0.w * wa + b0.w * wb;
        acc[4] += a1.x * wa + b1.x * wb; acc[5] += a1.y * wa + b1.y * wb;
        acc[6] += a1.z * wa + b1.z * wb; acc[7] += a1.w * wa + b1.w * wb;
    }
    if (j < end) {
        unsigned pa = d_sep[j];
        int sa = pa & 0xFFFFu, ta = pa >> 16;
        float wa = __expf(lrelu(d_hl1[sa * 4 + hsel] + hr + d_he1[ta * 4 + hsel]));
        const float4* pA = reinterpret_cast<const float4*>(&d_emb1[(size_t)sa * 256 + lane * 8]);
        float4 a0 = pA[0], a1 = pA[1];
        wsum += wa;
        acc[0] += a0.x * wa; acc[1] += a0.y * wa; acc[2] += a0.z * wa; acc[3] += a0.w * wa;
        acc[4] += a1.x * wa; acc[5] += a1.y * wa; acc[6] += a1.z * wa; acc[7] += a1.w * wa;
    }

    float inv = (wsum > 0.f) ? 1.f / wsum : 0.f;
    __nv_bfloat16 hi8[8], lo8[8];
#pragma unroll
    for (int i = 0; i < 8; i++) {
        float v = acc[i] * inv;
        v = (v > 0.f) ? v : expm1f(v);     // elu
        hi8[i] = __float2bfloat16(v);
        lo8[i] = __float2bfloat16(v - __bfloat162float(hi8[i]));
    }
    *reinterpret_cast<uint4*>(&d_h1_hi[(size_t)n * 256 + lane * 8]) = *reinterpret_cast<uint4*>(hi8);
    *reinterpret_cast<uint4*>(&d_h1_lo[(size_t)n * 256 + lane * 8]) = *reinterpret_cast<uint4*>(lo8);
}

// ---------------- layer2 node dots: warp per node ----------------
__global__ void nodedot2(const float* __restrict__ a_l, const float* __restrict__ a_r)
{
    int gid = blockIdx.x * blockDim.x + threadIdx.x;
    int n = gid >> 5;
    int lane = gid & 31;
    if (n >= NN) return;
    float2 v = *reinterpret_cast<const float2*>(&d_emb2[(size_t)n * 64 + lane * 2]);
    float2 al = *reinterpret_cast<const float2*>(&a_l[lane * 2]);
    float2 ar = *reinterpret_cast<const float2*>(&a_r[lane * 2]);
    float sl = v.x * al.x + v.y * al.y;
    float sr = v.x * ar.x + v.y * ar.y;
#pragma unroll
    for (int off = 16; off > 0; off >>= 1) {
        sl += __shfl_xor_sync(0xffffffffu, sl, off);
        sr += __shfl_xor_sync(0xffffffffu, sr, off);
    }
    if (lane == 0) { d_hl2[n] = sl; d_hr2[n] = sr; }
}

// ---------------- layer2: fused attention + aggregate + normalize + residual ----------------
__global__ void __launch_bounds__(256) agg2fin_kernel(const float* __restrict__ res_b2,
                                                      float* __restrict__ out)
{
    int gid = blockIdx.x * blockDim.x + threadIdx.x;
    int n = gid >> 5;
    int lane = gid & 31;
    if (n >= NN) return;
    int beg = d_ptr[n], end = d_ptr[n + 1];
    float hr = d_hr2[n];
    float ax = 0.f, ay = 0.f, wsum = 0.f;

    int j = beg;
    for (; j + 1 < end; j += 2) {
        unsigned pa = d_sep[j];
        unsigned pb = d_sep[j + 1];
        int sa = pa & 0xFFFFu, ta = pa >> 16;
        int sb = pb & 0xFFFFu, tb = pb >> 16;
        float wa = __expf(lrelu(d_hl2[sa] + hr + d_he2[ta]));
        float wb = __expf(lrelu(d_hl2[sb] + hr + d_he2[tb]));
        float2 va = *reinterpret_cast<const float2*>(&d_emb2[(size_t)sa * 64 + lane * 2]);
        float2 vb = *reinterpret_cast<const float2*>(&d_emb2[(size_t)sb * 64 + lane * 2]);
        wsum += wa + wb;
        ax += va.x * wa + vb.x * wb;
        ay += va.y * wa + vb.y * wb;
    }
    if (j < end) {
        unsigned pa = d_sep[j];
        int sa = pa & 0xFFFFu, ta = pa >> 16;
        float wa = __expf(lrelu(d_hl2[sa] + hr + d_he2[ta]));
        float2 va = *reinterpret_cast<const float2*>(&d_emb2[(size_t)sa * 64 + lane * 2]);
        wsum += wa;
        ax += va.x * wa;
        ay += va.y * wa;
    }

    float inv = (wsum > 0.f) ? 1.f / wsum : 0.f;
    float2 r = *reinterpret_cast<const float2*>(&d_res2[(size_t)n * 64 + lane * 2]);
    float2 b = *reinterpret_cast<const float2*>(&res_b2[lane * 2]);
    float2 o = make_float2(ax * inv + r.x + b.x, ay * inv + r.y + b.y);
    *reinterpret_cast<float2*>(&out[(size_t)n * 64 + lane * 2]) = o;
}

// ---------------- launch ----------------
extern "C" void kernel_launch(void* const* d_in, const int* in_sizes, int n_in,
                              void* d_out, int out_size)
{
    const float* h         = (const float*)d_in[0];
    const int*   row       = (const int*)d_in[1];
    const int*   col       = (const int*)d_in[2];
    const int*   etype     = (const int*)d_in[3];
    const float* edge_emb1 = (const float*)d_in[4];
    const float* W1        = (const float*)d_in[5];
    const float* Wr1       = (const float*)d_in[6];
    const float* a_l1      = (const float*)d_in[7];
    const float* a_r1      = (const float*)d_in[8];
    const float* a_e1      = (const float*)d_in[9];
    const float* edge_emb2 = (const float*)d_in[10];
    const float* W2        = (const float*)d_in[11];
    const float* Wr2       = (const float*)d_in[12];
    const float* a_l2      = (const float*)d_in[13];
    const float* a_r2      = (const float*)d_in[14];
    const float* a_e2      = (const float*)d_in[15];
    const float* res_W2    = (const float*)d_in[16];
    const float* res_b2    = (const float*)d_in[17];
    float* out = (float*)d_out;

    float *p_emb1, *p_emb2, *p_res2;
    cudaGetSymbolAddress((void**)&p_emb1, d_emb1);
    cudaGetSymbolAddress((void**)&p_emb2, d_emb2);
    cudaGetSymbolAddress((void**)&p_res2, d_res2);
    __nv_bfloat16 *p_w1h, *p_w1l, *p_w2h, *p_w2l, *p_hh, *p_hl, *p_h1h, *p_h1l;
    cudaGetSymbolAddress((void**)&p_w1h, d_w1t_hi);
    cudaGetSymbolAddress((void**)&p_w1l, d_w1t_lo);
    cudaGetSymbolAddress((void**)&p_w2h, d_w2t_hi);
    cudaGetSymbolAddress((void**)&p_w2l, d_w2t_lo);
    cudaGetSymbolAddress((void**)&p_hh, d_h_hi);
    cudaGetSymbolAddress((void**)&p_hl, d_h_lo);
    cudaGetSymbolAddress((void**)&p_h1h, d_h1_hi);
    cudaGetSymbolAddress((void**)&p_h1l, d_h1_lo);

    // ---- prep ----
    prep_small<<<1, 1024>>>(edge_emb1, Wr1, a_e1, edge_emb2, Wr2, a_e2, W1, a_l1, a_r1); // #1
    prep_w<<<256, 256>>>(W1, W2, res_W2);                                                // #2
    prep_hlr<<<(NN * 32 + 255) / 256, 256>>>(h);                                         // #3

    // ---- layer 1 GEMM (profiled slot #4) ----
    mma_gemm<0><<<dim3(2, 391), 256>>>(p_hh, p_hl, p_w1h, p_w1l, p_emb1, nullptr, NN);   // #4

    // ---- CSR build ----
    init_kernel<<<(NN + 255) / 256, 256>>>();                                            // #5
    hist_kernel<<<(EE + 255) / 256, 256>>>(col);                                         // #6
    scan_kernel<<<1, 1024>>>();                                                          // #7
    scatter_kernel<<<(EE + 255) / 256, 256>>>(row, col, etype);                          // #8

    // ---- layer 1 edge phase ----
    agg1fin_kernel<<<(NN * 32) / 256, 256>>>();                                          // #9

    // ---- layer 2 ----
    mma_gemm<1><<<dim3(1, 391), 256>>>(p_h1h, p_h1l, p_w2h, p_w2l, p_emb2, p_res2, NN);  // #10
    nodedot2<<<(NN * 32 + 255) / 256, 256>>>(a_l2, a_r2);                                // #11
    agg2fin_kernel<<<(NN * 32) / 256, 256>>>(res_b2, out);                               // #12
}

// round 6
// speedup vs baseline: 1.1137x; 1.0615x over previous
#include <cuda_runtime.h>
#include <cuda_bf16.h>
#include <math.h>

#define NN 50000
#define EE 500000
#define IN_DIM 256
#define SLOPE 0.2f
#define NT 8
#define ED 32

// ---------------- scratch (device globals; no allocs allowed) ----------------
__device__ __align__(16) float d_emb1[NN * 256];
__device__ __align__(16) float d_hl1[NN * 4];
__device__ __align__(16) float d_hr1[NN * 4];

__device__ __align__(16) float d_emb2[NN * 64];
__device__ __align__(16) float d_res2[NN * 64];
__device__ float d_hl2[NN];
__device__ float d_hr2[NN];

__device__ __align__(16) float d_he1[NT * 4];
__device__ float d_he2[NT];
__device__ __align__(16) float d_av1[IN_DIM * 4];
__device__ __align__(16) float d_ar1[IN_DIM * 4];

// CSR by destination; payload = src | (etype << 16)
__device__ int d_deg[NN];
__device__ int d_ptr[NN + 1];
__device__ int d_cur[NN];
__device__ unsigned d_sep[EE];

// split-bf16 operands (padded by 128 rows so GEMM A-loads need no bounds check)
#define NPAD (NN + 128)
__device__ __align__(16) __nv_bfloat16 d_h_hi[NPAD * 256];
__device__ __align__(16) __nv_bfloat16 d_h_lo[NPAD * 256];
__device__ __align__(16) __nv_bfloat16 d_h1_hi[NPAD * 256];
__device__ __align__(16) __nv_bfloat16 d_h1_lo[NPAD * 256];
__device__ __align__(16) __nv_bfloat16 d_w1t_hi[256 * 256];
__device__ __align__(16) __nv_bfloat16 d_w1t_lo[256 * 256];
__device__ __align__(16) __nv_bfloat16 d_w2t_hi[128 * 256];
__device__ __align__(16) __nv_bfloat16 d_w2t_lo[128 * 256];

// ---------------- helpers ----------------
__device__ __forceinline__ float lrelu(float x) { return x >= 0.f ? x : SLOPE * x; }

__device__ __forceinline__ unsigned sptr(const void* p) {
    return (unsigned)__cvta_generic_to_shared(p);
}
__device__ __forceinline__ void ldmx4(unsigned* r, unsigned addr) {
    asm volatile("ldmatrix.sync.aligned.m8n8.x4.shared.b16 {%0,%1,%2,%3}, [%4];"
                 : "=r"(r[0]), "=r"(r[1]), "=r"(r[2]), "=r"(r[3]) : "r"(addr));
}
__device__ __forceinline__ void mma_bf16(float* c, const unsigned* a, const unsigned* b) {
    asm volatile("mma.sync.aligned.m16n8k16.row.col.f32.bf16.bf16.f32 "
                 "{%0,%1,%2,%3},{%4,%5,%6,%7},{%8,%9},{%0,%1,%2,%3};"
                 : "+f"(c[0]), "+f"(c[1]), "+f"(c[2]), "+f"(c[3])
                 : "r"(a[0]), "r"(a[1]), "r"(a[2]), "r"(a[3]),
                   "r"(b[0]), "r"(b[1]));
}
__device__ __forceinline__ void cpa16(void* s, const void* g) {
    asm volatile("cp.async.cg.shared.global [%0], [%1], 16;"
                 :: "r"(sptr(s)), "l"(g) : "memory");
}
__device__ __forceinline__ void cpa_commit() {
    asm volatile("cp.async.commit_group;" ::: "memory");
}
template<int N>
__device__ __forceinline__ void cpa_wait() {
    asm volatile("cp.async.wait_group %0;" :: "n"(N) : "memory");
}

// ---------------- tiny precompute ----------------
__global__ void prep_small(const float* __restrict__ edge_emb1,
                           const float* __restrict__ Wr1,
                           const float* __restrict__ a_e1,
                           const float* __restrict__ edge_emb2,
                           const float* __restrict__ Wr2,
                           const float* __restrict__ a_e2,
                           const float* __restrict__ W1,
                           const float* __restrict__ a_l1,
                           const float* __restrict__ a_r1)
{
    int tid = threadIdx.x;
    {
        int k = tid >> 2, hh = tid & 3;
        float sl = 0.f, sr = 0.f;
        for (int d = 0; d < 64; d++) {
            float w = W1[k * 256 + hh * 64 + d];
            sl += w * a_l1[hh * 64 + d];
            sr += w * a_r1[hh * 64 + d];
        }
        d_av1[tid] = sl;
        d_ar1[tid] = sr;
    }
    if (tid < NT * 4) {
        int t = tid >> 2, h = tid & 3;
        float s = 0.f;
        for (int ed = 0; ed < ED; ed++) {
            float ee = 0.f;
            for (int e = 0; e < ED; e++)
                ee += edge_emb1[t * ED + e] * Wr1[(t * ED + e) * 128 + h * ED + ed];
            s += ee * a_e1[h * ED + ed];
        }
        d_he1[t * 4 + h] = s;
    } else if (tid < NT * 4 + NT) {
        int t = tid - NT * 4;
        float s = 0.f;
        for (int ed = 0; ed < ED; ed++) {
            float ee = 0.f;
            for (int e = 0; e < ED; e++)
                ee += edge_emb2[t * ED + e] * Wr2[(t * ED + e) * ED + ed];
            s += ee * a_e2[ed];
        }
        d_he2[t] = s;
    }
}

// ---------------- weight transpose + hi/lo split ----------------
__global__ void prep_w(const float* __restrict__ W1,
                       const float* __restrict__ W2,
                       const float* __restrict__ res_W2)
{
    int idx = blockIdx.x * blockDim.x + threadIdx.x;
    if (idx < 256 * 256) {
        int n = idx >> 8, k = idx & 255;
        float v = W1[k * 256 + n];
        __nv_bfloat16 hi = __float2bfloat16(v);
        __nv_bfloat16 lo = __float2bfloat16(v - __bfloat162float(hi));
        d_w1t_hi[n * 256 + k] = hi;
        d_w1t_lo[n * 256 + k] = lo;
    }
    if (idx < 128 * 256) {
        int n = idx >> 8, k = idx & 255;
        int kd = (k & 63) * 4 + (k >> 6);
        float v = (n < 64) ? W2[kd * 64 + n] : res_W2[kd * 64 + (n - 64)];
        __nv_bfloat16 hi = __float2bfloat16(v);
        __nv_bfloat16 lo = __float2bfloat16(v - __bfloat162float(hi));
        d_w2t_hi[n * 256 + k] = hi;
        d_w2t_lo[n * 256 + k] = lo;
    }
}

// ---------------- fused: split h into hi/lo bf16 + layer1 node dots ----------------
__global__ void __launch_bounds__(256) prep_hlr(const float* __restrict__ h)
{
    int gid = blockIdx.x * blockDim.x + threadIdx.x;
    int n = gid >> 5;
    int lane = gid & 31;
    if (n >= NN) return;
    float al[4] = {}, ar[4] = {};
#pragma unroll
    for (int it = 0; it < 4; it++) {
        int k = it * 64 + lane * 2;
        float2 v = *reinterpret_cast<const float2*>(&h[(size_t)n * 256 + k]);
        float4 a0 = *reinterpret_cast<const float4*>(&d_av1[k * 4]);
        float4 a1 = *reinterpret_cast<const float4*>(&d_av1[k * 4 + 4]);
        float4 r0 = *reinterpret_cast<const float4*>(&d_ar1[k * 4]);
        float4 r1 = *reinterpret_cast<const float4*>(&d_ar1[k * 4 + 4]);
        al[0] += v.x * a0.x + v.y * a1.x; al[1] += v.x * a0.y + v.y * a1.y;
        al[2] += v.x * a0.z + v.y * a1.z; al[3] += v.x * a0.w + v.y * a1.w;
        ar[0] += v.x * r0.x + v.y * r1.x; ar[1] += v.x * r0.y + v.y * r1.y;
        ar[2] += v.x * r0.z + v.y * r1.z; ar[3] += v.x * r0.w + v.y * r1.w;
        __nv_bfloat16 hx = __float2bfloat16(v.x);
        __nv_bfloat16 hy = __float2bfloat16(v.y);
        __nv_bfloat16 lx = __float2bfloat16(v.x - __bfloat162float(hx));
        __nv_bfloat16 ly = __float2bfloat16(v.y - __bfloat162float(hy));
        __nv_bfloat162 hp; hp.x = hx; hp.y = hy;
        __nv_bfloat162 lp; lp.x = lx; lp.y = ly;
        *reinterpret_cast<__nv_bfloat162*>(&d_h_hi[(size_t)n * 256 + k]) = hp;
        *reinterpret_cast<__nv_bfloat162*>(&d_h_lo[(size_t)n * 256 + k]) = lp;
    }
#pragma unroll
    for (int off = 16; off > 0; off >>= 1) {
#pragma unroll
        for (int j = 0; j < 4; j++) {
            al[j] += __shfl_xor_sync(0xffffffffu, al[j], off);
            ar[j] += __shfl_xor_sync(0xffffffffu, ar[j], off);
        }
    }
    if (lane == 0) {
        *reinterpret_cast<float4*>(&d_hl1[n * 4]) = make_float4(al[0], al[1], al[2], al[3]);
        *reinterpret_cast<float4*>(&d_hr1[n * 4]) = make_float4(ar[0], ar[1], ar[2], ar[3]);
    }
}

// ---------------- tensor-core GEMM, split-bf16, 2-stage cp.async pipeline ----------------
// dynamic smem layout (bf16 elems): A: [stage][split][128][40], B after at +20480
#define AS_IDX(st, sp, r, c) ((st) * 10240 + (sp) * 5120 + (r) * 40 + (c))
#define BS_IDX(st, sp, r, c) (20480 + (st) * 10240 + (sp) * 5120 + (r) * 40 + (c))
#define GEMM_SMEM (40960 * 2)   // bytes

template<int MODE>
__global__ void __launch_bounds__(256) mma_gemm(const __nv_bfloat16* __restrict__ Ahi,
                                                const __nv_bfloat16* __restrict__ Alo,
                                                const __nv_bfloat16* __restrict__ Bhi,
                                                const __nv_bfloat16* __restrict__ Blo,
                                                float* __restrict__ C0,
                                                float* __restrict__ C1,
                                                int M)
{
    extern __shared__ __nv_bfloat16 sm[];

    const int tid = threadIdx.x;
    const int lane = tid & 31;
    const int warp = tid >> 5;
    const int wm = warp & 1;
    const int wn = warp >> 1;
    const int rowBase = blockIdx.y * 128;
    const int colBase = blockIdx.x * 128;

    float acc[4][4][4];
#pragma unroll
    for (int i = 0; i < 4; i++)
#pragma unroll
        for (int j = 0; j < 4; j++)
#pragma unroll
            for (int q = 0; q < 4; q++) acc[i][j][q] = 0.f;

    const int grp = lane >> 3;
    const int arow = (lane & 7) + ((grp & 1) << 3);
    const int acol = (grp >> 1) << 3;
    const int brow = (lane & 7) + ((grp >> 1) << 3);
    const int bcol = (grp & 1) << 3;

    // per-thread load coordinates (16B each)
    const int lr = tid >> 2;            // 0..63 (x4 via +64 strides handled below)
    const int lc = (tid & 3) * 8;

    // stage loader: A rows are pad-safe (arrays padded), B always in range
    auto load_stage = [&](int st, int k0) {
#pragma unroll
        for (int it = 0; it < 2; it++) {
            int r = lr + it * 64;
            size_t offA = (size_t)(rowBase + r) * 256 + k0 + lc;
            cpa16(&sm[AS_IDX(st, 0, r, lc)], &Ahi[offA]);
            cpa16(&sm[AS_IDX(st, 1, r, lc)], &Alo[offA]);
            size_t offB = (size_t)(colBase + r) * 256 + k0 + lc;
            cpa16(&sm[BS_IDX(st, 0, r, lc)], &Bhi[offB]);
            cpa16(&sm[BS_IDX(st, 1, r, lc)], &Blo[offB]);
        }
    };

    load_stage(0, 0);
    cpa_commit();

    int st = 0;
    for (int k0 = 0; k0 < 256; k0 += 32, st ^= 1) {
        if (k0 + 32 < 256) {
            load_stage(st ^ 1, k0 + 32);
            cpa_commit();
            cpa_wait<1>();
        } else {
            cpa_wait<0>();
        }
        __syncthreads();

#pragma unroll
        for (int ks = 0; ks < 2; ks++) {
            unsigned afr[4][2][4];
            unsigned bfr[4][2][2];
#pragma unroll
            for (int mt = 0; mt < 4; mt++)
#pragma unroll
                for (int s = 0; s < 2; s++)
                    ldmx4(afr[mt][s],
                          sptr(&sm[AS_IDX(st, s, wm * 64 + mt * 16 + arow, ks * 16 + acol)]));
#pragma unroll
            for (int np = 0; np < 2; np++)
#pragma unroll
                for (int s = 0; s < 2; s++) {
                    unsigned r4[4];
                    ldmx4(r4, sptr(&sm[BS_IDX(st, s, wn * 32 + np * 16 + brow, ks * 16 + bcol)]));
                    bfr[np * 2 + 0][s][0] = r4[0]; bfr[np * 2 + 0][s][1] = r4[1];
                    bfr[np * 2 + 1][s][0] = r4[2]; bfr[np * 2 + 1][s][1] = r4[3];
                }
#pragma unroll
            for (int mt = 0; mt < 4; mt++)
#pragma unroll
                for (int nt = 0; nt < 4; nt++) {
                    mma_bf16(acc[mt][nt], afr[mt][0], bfr[nt][0]);
                    mma_bf16(acc[mt][nt], afr[mt][0], bfr[nt][1]);
                    mma_bf16(acc[mt][nt], afr[mt][1], bfr[nt][0]);
                }
        }
        __syncthreads();
    }

#pragma unroll
    for (int mt = 0; mt < 4; mt++) {
#pragma unroll
        for (int nt = 0; nt < 4; nt++) {
            int cc = colBase + wn * 32 + nt * 8 + (lane & 3) * 2;
#pragma unroll
            for (int hh = 0; hh < 2; hh++) {
                int gm = rowBase + wm * 64 + mt * 16 + (lane >> 2) + hh * 8;
                if (gm >= M) continue;
                float2 v = make_float2(acc[mt][nt][hh * 2], acc[mt][nt][hh * 2 + 1]);
                if (MODE == 0) {
                    *reinterpret_cast<float2*>(&C0[(size_t)gm * 256 + cc]) = v;
                } else {
                    if (cc < 64)
                        *reinterpret_cast<float2*>(&C0[(size_t)gm * 64 + cc]) = v;
                    else
                        *reinterpret_cast<float2*>(&C1[(size_t)gm * 64 + cc - 64]) = v;
                }
            }
        }
    }
}

// ---------------- CSR build ----------------
__global__ void init_kernel() {
    int i = blockIdx.x * blockDim.x + threadIdx.x;
    if (i < NN) d_deg[i] = 0;
}

__global__ void hist_kernel(const int* __restrict__ col) {
    int e = blockIdx.x * blockDim.x + threadIdx.x;
    if (e < EE) atomicAdd(&d_deg[col[e]], 1);
}

__global__ void scan_kernel() {
    __shared__ int sh[1024];
    const int PER = 49;
    int t = threadIdx.x;
    int base = t * PER;
    int local = 0;
    for (int i = 0; i < PER; i++) {
        int n = base + i;
        if (n < NN) local += d_deg[n];
    }
    sh[t] = local;
    __syncthreads();
    for (int off = 1; off < 1024; off <<= 1) {
        int v = (t >= off) ? sh[t - off] : 0;
        __syncthreads();
        sh[t] += v;
        __syncthreads();
    }
    int run = (t > 0) ? sh[t - 1] : 0;
    for (int i = 0; i < PER; i++) {
        int n = base + i;
        if (n < NN) {
            d_ptr[n] = run;
            d_cur[n] = run;
            run += d_deg[n];
        }
    }
    if (t == 0) d_ptr[NN] = EE;
}

__global__ void scatter_kernel(const int* __restrict__ row, const int* __restrict__ col,
                               const int* __restrict__ et) {
    int e = blockIdx.x * blockDim.x + threadIdx.x;
    if (e >= EE) return;
    int c = col[e];
    int pos = atomicAdd(&d_cur[c], 1);
    d_sep[pos] = (unsigned)row[e] | ((unsigned)et[e] << 16);
}

// ---------------- layer1: fused attention + aggregate + softmax + ELU + split ----------------
__global__ void __launch_bounds__(256) agg1fin_kernel()
{
    int gid = blockIdx.x * blockDim.x + threadIdx.x;
    int n = gid >> 5;
    int lane = gid & 31;
    if (n >= NN) return;
    int beg = d_ptr[n], end = d_ptr[n + 1];
    int hsel = lane >> 3;
    float hr = d_hr1[n * 4 + hsel];
    float acc[8] = {};
    float wsum = 0.f;

    int j = beg;
    for (; j + 3 < end; j += 4) {
        unsigned p0 = __ldg(&d_sep[j + 0]);
        unsigned p1 = __ldg(&d_sep[j + 1]);
        unsigned p2 = __ldg(&d_sep[j + 2]);
        unsigned p3 = __ldg(&d_sep[j + 3]);
        int s0 = p0 & 0xFFFFu, s1 = p1 & 0xFFFFu, s2 = p2 & 0xFFFFu, s3 = p3 & 0xFFFFu;
        float w0 = __expf(lrelu(d_hl1[s0 * 4 + hsel] + hr + d_he1[(p0 >> 16) * 4 + hsel]));
        float w1 = __expf(lrelu(d_hl1[s1 * 4 + hsel] + hr + d_he1[(p1 >> 16) * 4 + hsel]));
        float w2 = __expf(lrelu(d_hl1[s2 * 4 + hsel] + hr + d_he1[(p2 >> 16) * 4 + hsel]));
        float w3 = __expf(lrelu(d_hl1[s3 * 4 + hsel] + hr + d_he1[(p3 >> 16) * 4 + hsel]));
        const float4* q0 = reinterpret_cast<const float4*>(&d_emb1[(size_t)s0 * 256 + lane * 8]);
        const float4* q1 = reinterpret_cast<const float4*>(&d_emb1[(size_t)s1 * 256 + lane * 8]);
        const float4* q2 = reinterpret_cast<const float4*>(&d_emb1[(size_t)s2 * 256 + lane * 8]);
        const float4* q3 = reinterpret_cast<const float4*>(&d_emb1[(size_t)s3 * 256 + lane * 8]);
        float4 a0 = __ldg(q0), a1 = __ldg(q0 + 1);
        float4 b0 = __ldg(q1), b1 = __ldg(q1 + 1);
        float4 c0 = __ldg(q2), c1 = __ldg(q2 + 1);
        float4 e0 = __ldg(q3), e1 = __ldg(q3 + 1);
        wsum += (w0 + w1) + (w2 + w3);
        acc[0] += a0.x * w0 + b0.x * w1 + c0.x * w2 + e0.x * w3;
        acc[1] += a0.y * w0 + b0.y * w1 + c0.y * w2 + e0.y * w3;
        acc[2] += a0.z * w0 + b0.z * w1 + c0.z * w2 + e0.z * w3;
        acc[3] += a0.w * w0 + b0.w * w1 + c0.w * w2 + e0.w * w3;
        acc[4] += a1.x * w0 + b1.x * w1 + c1.x * w2 + e1.x * w3;
        acc[5] += a1.y * w0 + b1.y * w1 + c1.y * w2 + e1.y * w3;
        acc[6] += a1.z * w0 + b1.z * w1 + c1.z * w2 + e1.z * w3;
        acc[7] += a1.w * w0 + b1.w * w1 + c1.w * w2 + e1.w * w3;
    }
    for (; j < end; j++) {
        unsigned pa = __ldg(&d_sep[j]);
        int sa = pa & 0xFFFFu;
        float wa = __expf(lrelu(d_hl1[sa * 4 + hsel] + hr + d_he1[(pa >> 16) * 4 + hsel]));
        const float4* pA = reinterpret_cast<const float4*>(&d_emb1[(size_t)sa * 256 + lane * 8]);
        float4 a0 = __ldg(pA), a1 = __ldg(pA + 1);
        wsum += wa;
        acc[0] += a0.x * wa; acc[1] += a0.y * wa; acc[2] += a0.z * wa; acc[3] += a0.w * wa;
        acc[4] += a1.x * wa; acc[5] += a1.y * wa; acc[6] += a1.z * wa; acc[7] += a1.w * wa;
    }

    float inv = (wsum > 0.f) ? 1.f / wsum : 0.f;
    __nv_bfloat16 hi8[8], lo8[8];
#pragma unroll
    for (int i = 0; i < 8; i++) {
        float v = acc[i] * inv;
        v = (v > 0.f) ? v : expm1f(v);
        hi8[i] = __float2bfloat16(v);
        lo8[i] = __float2bfloat16(v - __bfloat162float(hi8[i]));
    }
    *reinterpret_cast<uint4*>(&d_h1_hi[(size_t)n * 256 + lane * 8]) = *reinterpret_cast<uint4*>(hi8);
    *reinterpret_cast<uint4*>(&d_h1_lo[(size_t)n * 256 + lane * 8]) = *reinterpret_cast<uint4*>(lo8);
}

// ---------------- layer2 node dots ----------------
__global__ void nodedot2(const float* __restrict__ a_l, const float* __restrict__ a_r)
{
    int gid = blockIdx.x * blockDim.x + threadIdx.x;
    int n = gid >> 5;
    int lane = gid & 31;
    if (n >= NN) return;
    float2 v = *reinterpret_cast<const float2*>(&d_emb2[(size_t)n * 64 + lane * 2]);
    float2 al = *reinterpret_cast<const float2*>(&a_l[lane * 2]);
    float2 ar = *reinterpret_cast<const float2*>(&a_r[lane * 2]);
    float sl = v.x * al.x + v.y * al.y;
    float sr = v.x * ar.x + v.y * ar.y;
#pragma unroll
    for (int off = 16; off > 0; off >>= 1) {
        sl += __shfl_xor_sync(0xffffffffu, sl, off);
        sr += __shfl_xor_sync(0xffffffffu, sr, off);
    }
    if (lane == 0) { d_hl2[n] = sl; d_hr2[n] = sr; }
}

// ---------------- layer2: fused attention + aggregate + normalize + residual ----------------
__global__ void __launch_bounds__(256) agg2fin_kernel(const float* __restrict__ res_b2,
                                                      float* __restrict__ out)
{
    int gid = blockIdx.x * blockDim.x + threadIdx.x;
    int n = gid >> 5;
    int lane = gid & 31;
    if (n >= NN) return;
    int beg = d_ptr[n], end = d_ptr[n + 1];
    float hr = d_hr2[n];
    float ax = 0.f, ay = 0.f, wsum = 0.f;

    int j = beg;
    for (; j + 3 < end; j += 4) {
        unsigned p0 = __ldg(&d_sep[j + 0]);
        unsigned p1 = __ldg(&d_sep[j + 1]);
        unsigned p2 = __ldg(&d_sep[j + 2]);
        unsigned p3 = __ldg(&d_sep[j + 3]);
        int s0 = p0 & 0xFFFFu, s1 = p1 & 0xFFFFu, s2 = p2 & 0xFFFFu, s3 = p3 & 0xFFFFu;
        float w0 = __expf(lrelu(d_hl2[s0] + hr + d_he2[p0 >> 16]));
        float w1 = __expf(lrelu(d_hl2[s1] + hr + d_he2[p1 >> 16]));
        float w2 = __expf(lrelu(d_hl2[s2] + hr + d_he2[p2 >> 16]));
        float w3 = __expf(lrelu(d_hl2[s3] + hr + d_he2[p3 >> 16]));
        float2 v0 = __ldg(reinterpret_cast<const float2*>(&d_emb2[(size_t)s0 * 64 + lane * 2]));
        float2 v1 = __ldg(reinterpret_cast<const float2*>(&d_emb2[(size_t)s1 * 64 + lane * 2]));
        float2 v2 = __ldg(reinterpret_cast<const float2*>(&d_emb2[(size_t)s2 * 64 + lane * 2]));
        float2 v3 = __ldg(reinterpret_cast<const float2*>(&d_emb2[(size_t)s3 * 64 + lane * 2]));
        wsum += (w0 + w1) + (w2 + w3);
        ax += v0.x * w0 + v1.x * w1 + v2.x * w2 + v3.x * w3;
        ay += v0.y * w0 + v1.y * w1 + v2.y * w2 + v3.y * w3;
    }
    for (; j < end; j++) {
        unsigned pa = __ldg(&d_sep[j]);
        int sa = pa & 0xFFFFu;
        float wa = __expf(lrelu(d_hl2[sa] + hr + d_he2[pa >> 16]));
        float2 va = __ldg(reinterpret_cast<const float2*>(&d_emb2[(size_t)sa * 64 + lane * 2]));
        wsum += wa;
        ax += va.x * wa;
        ay += va.y * wa;
    }

    float inv = (wsum > 0.f) ? 1.f / wsum : 0.f;
    float2 r = *reinterpret_cast<const float2*>(&d_res2[(size_t)n * 64 + lane * 2]);
    float2 b = *reinterpret_cast<const float2*>(&res_b2[lane * 2]);
    float2 o = make_float2(ax * inv + r.x + b.x, ay * inv + r.y + b.y);
    *reinterpret_cast<float2*>(&out[(size_t)n * 64 + lane * 2]) = o;
}

// ---------------- launch ----------------
extern "C" void kernel_launch(void* const* d_in, const int* in_sizes, int n_in,
                              void* d_out, int out_size)
{
    const float* h         = (const float*)d_in[0];
    const int*   row       = (const int*)d_in[1];
    const int*   col       = (const int*)d_in[2];
    const int*   etype     = (const int*)d_in[3];
    const float* edge_emb1 = (const float*)d_in[4];
    const float* W1        = (const float*)d_in[5];
    const float* Wr1       = (const float*)d_in[6];
    const float* a_l1      = (const float*)d_in[7];
    const float* a_r1      = (const float*)d_in[8];
    const float* a_e1      = (const float*)d_in[9];
    const float* edge_emb2 = (const float*)d_in[10];
    const float* W2        = (const float*)d_in[11];
    const float* Wr2       = (const float*)d_in[12];
    const float* a_l2      = (const float*)d_in[13];
    const float* a_r2      = (const float*)d_in[14];
    const float* a_e2      = (const float*)d_in[15];
    const float* res_W2    = (const float*)d_in[16];
    const float* res_b2    = (const float*)d_in[17];
    float* out = (float*)d_out;

    float *p_emb1, *p_emb2, *p_res2;
    cudaGetSymbolAddress((void**)&p_emb1, d_emb1);
    cudaGetSymbolAddress((void**)&p_emb2, d_emb2);
    cudaGetSymbolAddress((void**)&p_res2, d_res2);
    __nv_bfloat16 *p_w1h, *p_w1l, *p_w2h, *p_w2l, *p_hh, *p_hl, *p_h1h, *p_h1l;
    cudaGetSymbolAddress((void**)&p_w1h, d_w1t_hi);
    cudaGetSymbolAddress((void**)&p_w1l, d_w1t_lo);
    cudaGetSymbolAddress((void**)&p_w2h, d_w2t_hi);
    cudaGetSymbolAddress((void**)&p_w2l, d_w2t_lo);
    cudaGetSymbolAddress((void**)&p_hh, d_h_hi);
    cudaGetSymbolAddress((void**)&p_hl, d_h_lo);
    cudaGetSymbolAddress((void**)&p_h1h, d_h1_hi);
    cudaGetSymbolAddress((void**)&p_h1l, d_h1_lo);

    cudaFuncSetAttribute(mma_gemm<0>, cudaFuncAttributeMaxDynamicSharedMemorySize, GEMM_SMEM);
    cudaFuncSetAttribute(mma_gemm<1>, cudaFuncAttributeMaxDynamicSharedMemorySize, GEMM_SMEM);

    // ---- prep ----
    prep_small<<<1, 1024>>>(edge_emb1, Wr1, a_e1, edge_emb2, Wr2, a_e2, W1, a_l1, a_r1); // #1
    prep_w<<<256, 256>>>(W1, W2, res_W2);                                                // #2
    prep_hlr<<<(NN * 32 + 255) / 256, 256>>>(h);                                         // #3

    // ---- layer 1 GEMM (profiled slot #4) ----
    mma_gemm<0><<<dim3(2, 391), 256, GEMM_SMEM>>>(p_hh, p_hl, p_w1h, p_w1l,
                                                  p_emb1, nullptr, NN);                  // #4

    // ---- CSR build ----
    init_kernel<<<(NN + 255) / 256, 256>>>();                                            // #5
    hist_kernel<<<(EE + 255) / 256, 256>>>(col);                                         // #6
    scan_kernel<<<1, 1024>>>();                                                          // #7
    scatter_kernel<<<(EE + 255) / 256, 256>>>(row, col, etype);                          // #8

    // ---- layer 1 edge phase ----
    agg1fin_kernel<<<(NN * 32) / 256, 256>>>();                                          // #9

    // ---- layer 2 ----
    mma_gemm<1><<<dim3(1, 391), 256, GEMM_SMEM>>>(p_h1h, p_h1l, p_w2h, p_w2l,
                                                  p_emb2, p_res2, NN);                   // #10
    nodedot2<<<(NN * 32 + 255) / 256, 256>>>(a_l2, a_r2);                                // #11
    agg2fin_kernel<<<(NN * 32) / 256, 256>>>(res_b2, out);                               // #12
}